// round 2
// baseline (speedup 1.0000x reference)
#include <cuda_runtime.h>
#include <cuda_bf16.h>

// ConvSSM parallel scan, computed directly in the spatial domain.
// h_t = A (*) h_{t-1} + B (*) x_t, where (*) is circular convolution on the
// 64x64 torus (== the 2Hx2W zero-padded-FFT product in the reference).
// Output = h_t cropped to the top-left 32x32.
//
// One CTA per (b,c) chain (64 CTAs). h state double-buffered in SMEM.

#define NT 64   // timesteps
#define NB 2    // batch
#define NC 32   // channels
#define NH 32   // H
#define NW 32   // W
#define DD 64   // torus dim (2H = 2W)
#define PITCH 65
#define NTHREADS 512

__global__ __launch_bounds__(NTHREADS, 1)
void convssm_scan_kernel(const float* __restrict__ x,
                         const float* __restrict__ Ak,
                         const float* __restrict__ Bk,
                         float* __restrict__ out)
{
    __shared__ float hbuf[2][DD * PITCH];
    __shared__ float xs[NH * NW];

    const int blk = blockIdx.x;
    const int b   = blk / NC;
    const int c   = blk % NC;
    const int tid = threadIdx.x;
    const int tx  = tid & 15;    // 0..15 -> column group
    const int ty  = tid >> 4;    // 0..31 -> row group
    const int col0 = tx << 2;    // 4 cols per thread
    const int row0 = ty << 1;    // 2 rows per thread

    // Per-channel 3x3 kernels into registers (broadcast loads).
    float A[9], Bw[9];
#pragma unroll
    for (int i = 0; i < 9; ++i) {
        A[i]  = Ak[c * 9 + i];
        Bw[i] = Bk[c * 9 + i];
    }

    // t-invariant wrapped indices for the 4x6 patch gather.
    int ccol[6];
#pragma unroll
    for (int j = 0; j < 6; ++j) ccol[j] = (col0 - 2 + j) & 63;
    int crow[4];
#pragma unroll
    for (int i = 0; i < 4; ++i) crow[i] = ((row0 - 2 + i) & 63) * PITCH;

    // h_{-1} = 0
    for (int i = tid; i < DD * PITCH; i += NTHREADS) hbuf[0][i] = 0.0f;

    const size_t bc_off  = ((size_t)b * NC + c) * (NH * NW);
    const size_t tstride = (size_t)NB * NC * NH * NW;
    const float2* xin = (const float2*)(x + bc_off) + tid;
    float* obase = out + bc_off + row0 * NW + col0;
    const bool emits = (row0 < NH) && (col0 < NW);
    const bool bterm = (row0 < 34) && (col0 < 34);

    int cur = 0;
    for (int t = 0; t < NT; ++t) {
        // Load x_t (32x32) -> SMEM, coalesced float2 per thread.
        ((float2*)xs)[tid] = xin[(size_t)t * (tstride / 2)];
        __syncthreads();  // xs ready; also orders h zero-init / prev writes

        // Gather 4x6 patch of h_{t-1} around this thread's 2x4 tile
        // (circular indexing on the 64x64 torus).
        float p[4][6];
#pragma unroll
        for (int i = 0; i < 4; ++i) {
            const float* hr = &hbuf[cur][crow[i]];
#pragma unroll
            for (int j = 0; j < 6; ++j) {
                p[i][j] = hr[ccol[j]];
            }
        }

        // A-term: 3x3 conv, full reuse of the patch.
        float acc[2][4];
#pragma unroll
        for (int i = 0; i < 2; ++i) {
#pragma unroll
            for (int j = 0; j < 4; ++j) {
                float s = 0.0f;
#pragma unroll
                for (int dy = 0; dy < 3; ++dy) {
#pragma unroll
                    for (int dx = 0; dx < 3; ++dx) {
                        s = fmaf(A[dy * 3 + dx], p[i + 2 - dy][j + 2 - dx], s);
                    }
                }
                acc[i][j] = s;
            }
        }

        // B-term: x_t is nonzero only on [0,32)^2, so B(*)x_t has support
        // y,x in [0,34). Skip threads entirely outside that region.
        if (bterm) {
#pragma unroll
            for (int i = 0; i < 2; ++i) {
                const int y = row0 + i;
#pragma unroll
                for (int dy = 0; dy < 3; ++dy) {
                    const int ny = y - dy;               // wrap -> >= 32 -> zero
                    if ((unsigned)ny >= NH) continue;
                    const float* xrow = &xs[ny * NW];
#pragma unroll
                    for (int j = 0; j < 4; ++j) {
                        const int xx = col0 + j;
#pragma unroll
                        for (int dx = 0; dx < 3; ++dx) {
                            const int nx = xx - dx;
                            if ((unsigned)nx < NW)
                                acc[i][j] = fmaf(Bw[dy * 3 + dx], xrow[nx], acc[i][j]);
                        }
                    }
                }
            }
        }

        // Write h_t to the other buffer.
        const int nxt = cur ^ 1;
#pragma unroll
        for (int i = 0; i < 2; ++i) {
            float* hw = &hbuf[nxt][(row0 + i) * PITCH + col0];
#pragma unroll
            for (int j = 0; j < 4; ++j) hw[j] = acc[i][j];
        }

        // Emit cropped 32x32 output for this timestep (float4 stores).
        if (emits) {
            float* ob = obase + (size_t)t * tstride;
#pragma unroll
            for (int i = 0; i < 2; ++i) {
                float4 v = make_float4(acc[i][0], acc[i][1], acc[i][2], acc[i][3]);
                *(float4*)(ob + i * NW) = v;
            }
        }

        __syncthreads();  // h_t fully written, xs fully consumed
        cur = nxt;
    }
}

extern "C" void kernel_launch(void* const* d_in, const int* in_sizes, int n_in,
                              void* d_out, int out_size) {
    const float* x  = (const float*)d_in[0];
    const float* Ak = (const float*)d_in[1];
    const float* Bk = (const float*)d_in[2];
    float* out = (float*)d_out;
    convssm_scan_kernel<<<NB * NC, NTHREADS>>>(x, Ak, Bk, out);
}

// round 4
// speedup vs baseline: 1.9010x; 1.9010x over previous
#include <cuda_runtime.h>
#include <cuda_bf16.h>

// ConvSSM scan, spatial domain, two phases:
//   Phase 1 (u_precompute): U_t = B (*) x_t for all (t,b,c) — fully parallel.
//   Phase 2 (scan):         h_t = A (*) h_{t-1} + U_t  — 64 sequential steps,
//                           one CTA per (b,c) chain, h in SMEM with wrap halos.
// (*) = circular conv on the 64x64 torus (== reference's zero-padded FFT product).
// Output = h_t cropped to 32x32.

#define NT 64
#define NB 2
#define NC 32
#define NH 32
#define NW 32
#define NBC 64            // NB*NC chains
#define UP 40             // U pitch (floats)
#define UROWS 36          // U stored rows (support is 34, pad to 36)
#define HP 72             // h smem pitch (floats)
#define HROWS 68          // h smem rows (idx = actual + 4, halo at idx 0..3)

// Scratch for U: (T*NBC) slices of 36x40 floats = 23.6 MB.
__device__ __align__(16) float g_U[(size_t)NT * NBC * UROWS * UP];

// ---------------------------------------------------------------------------
// Phase 1: U[n][r][c] = sum_{dy,dx} B[dy][dx] * x_n[r-dy][c-dx], zero-padded x.
// One CTA per (t,b,c) slice n. 384 threads, 360 active outputs of float4.
// ---------------------------------------------------------------------------
__global__ __launch_bounds__(384)
void u_precompute(const float* __restrict__ x, const float* __restrict__ Bk)
{
    __shared__ __align__(16) float xs[38 * 44];   // idx = actual + 2, zero border
    const int n   = blockIdx.x;           // n = t*NBC + bc
    const int c   = n & (NC - 1);         // channel
    const int tid = threadIdx.x;

    for (int i = tid; i < 38 * 44; i += 384) xs[i] = 0.0f;
    __syncthreads();

    const float2* xsl = (const float2*)(x + (size_t)n * (NH * NW));
    for (int i = tid; i < (NH * NW) / 2; i += 384) {
        const int r = i >> 4, c2 = (i & 15) * 2;
        float2 v = xsl[i];
        *(float2*)&xs[(r + 2) * 44 + c2 + 2] = v;
    }

    float Bw[9];
#pragma unroll
    for (int j = 0; j < 9; ++j) Bw[j] = Bk[c * 9 + j];
    __syncthreads();

    if (tid < UROWS * (UP / 4)) {
        const int r  = tid / (UP / 4);
        const int c4 = tid % (UP / 4);
        float o[4] = {0.f, 0.f, 0.f, 0.f};
#pragma unroll
        for (int dy = 0; dy < 3; ++dy) {
            const float* rp = &xs[(r + 2 - dy) * 44 + c4 * 4 + 2];
#pragma unroll
            for (int j = 0; j < 4; ++j)
#pragma unroll
                for (int dx = 0; dx < 3; ++dx)
                    o[j] = fmaf(Bw[dy * 3 + dx], rp[j - dx], o[j]);
        }
        float4 v = make_float4(o[0], o[1], o[2], o[3]);
        *(float4*)&g_U[(size_t)n * (UROWS * UP) + r * UP + c4 * 4] = v;
    }
}

// ---------------------------------------------------------------------------
// Phase 2: sequential scan. One CTA of 512 threads per (b,c) chain.
// h layout: hb[row_idx][col_idx], idx = actual + 4.
//   halo: col idx 0..3  <- actual cols 60..63 (written by tx==15 threads)
//         row idx 2..3  <- actual rows 62..63 (written by row0==62 threads)
// Thread tile: 2 rows x 4 cols. Balanced row map: warp gets one low + one
// high row-pair (row0 = 2k + 32p).
// ---------------------------------------------------------------------------
__global__ __launch_bounds__(512, 1)
void convssm_scan(const float* __restrict__ Ak, float* __restrict__ out)
{
    __shared__ __align__(16) float hb[2][HROWS * HP];

    const int tid  = threadIdx.x;
    const int tx   = tid & 15;
    const int ty   = tid >> 4;
    const int p    = ty & 1;
    const int k    = ty >> 1;
    const int row0 = 2 * k + 32 * p;
    const int col0 = tx << 2;
    const int bc   = blockIdx.x;
    const int c    = bc & (NC - 1);

    float A[9];
#pragma unroll
    for (int j = 0; j < 9; ++j) A[j] = Ak[c * 9 + j];

    // h_{-1} = 0 (buffer 0 fully zeroed, including halos)
    for (int i = tid; i < HROWS * HP; i += 512) hb[0][i] = 0.0f;

    const bool uload = (row0 <= 34) && (tx <= 8);
    const bool emits = (p == 0) && (tx < 8);
    const bool chalo = (tx == 15);
    const bool rhalo = (row0 == 62);

    const float* Ubase = g_U + (size_t)bc * (UROWS * UP) + row0 * UP + col0;
    const size_t ustep = (size_t)NBC * (UROWS * UP);
    float* obase = out + (size_t)bc * (NH * NW) + row0 * NW + col0;
    const size_t ostep = (size_t)NBC * (NH * NW);

    // Prefetch U_0
    float u[2][4] = {{0.f,0.f,0.f,0.f},{0.f,0.f,0.f,0.f}};
    if (uload) {
        float4 a = *(const float4*)(Ubase);
        float4 b = *(const float4*)(Ubase + UP);
        u[0][0]=a.x; u[0][1]=a.y; u[0][2]=a.z; u[0][3]=a.w;
        u[1][0]=b.x; u[1][1]=b.y; u[1][2]=b.z; u[1][3]=b.w;
    }

    __syncthreads();

    int cur = 0;
    for (int t = 0; t < NT; ++t) {
        // Gather 4x6 patch of h_{t-1} (rows idx row0+2..+5, cols idx col0+2..+7)
        const float* pb = &hb[cur][(row0 + 2) * HP + col0 + 2];
        float pr[4][6];
#pragma unroll
        for (int i = 0; i < 4; ++i) {
            float2 a = *(const float2*)(pb + i * HP);
            float4 b = *(const float4*)(pb + i * HP + 2);
            pr[i][0] = a.x; pr[i][1] = a.y;
            pr[i][2] = b.x; pr[i][3] = b.y; pr[i][4] = b.z; pr[i][5] = b.w;
        }

        // acc = U_t (prefetched) + A (*) h_{t-1}
        float acc[2][4];
#pragma unroll
        for (int i = 0; i < 2; ++i)
#pragma unroll
            for (int j = 0; j < 4; ++j) {
                float s = u[i][j];
#pragma unroll
                for (int dy = 0; dy < 3; ++dy)
#pragma unroll
                    for (int dx = 0; dx < 3; ++dx)
                        s = fmaf(A[dy * 3 + dx], pr[i + 2 - dy][j + 2 - dx], s);
                acc[i][j] = s;
            }

        // Prefetch U_{t+1}
        if (uload && t + 1 < NT) {
            const float* up = Ubase + (size_t)(t + 1) * ustep;
            float4 a = *(const float4*)(up);
            float4 b = *(const float4*)(up + UP);
            u[0][0]=a.x; u[0][1]=a.y; u[0][2]=a.z; u[0][3]=a.w;
            u[1][0]=b.x; u[1][1]=b.y; u[1][2]=b.z; u[1][3]=b.w;
        }

        // Write h_t (+ wrap halos)
        const int nxt = cur ^ 1;
        float4 a0 = make_float4(acc[0][0], acc[0][1], acc[0][2], acc[0][3]);
        float4 a1 = make_float4(acc[1][0], acc[1][1], acc[1][2], acc[1][3]);
        float* wb = &hb[nxt][(row0 + 4) * HP + col0 + 4];
        *(float4*)(wb)      = a0;
        *(float4*)(wb + HP) = a1;
        if (chalo) {                       // actual cols 60..63 -> col idx 0..3
            *(float4*)(wb - 64)      = a0;
            *(float4*)(wb - 64 + HP) = a1;
        }
        if (rhalo) {                       // actual rows 62..63 -> row idx 2..3
            float* hw = &hb[nxt][2 * HP + col0 + 4];
            *(float4*)(hw)      = a0;
            *(float4*)(hw + HP) = a1;
            if (chalo) {
                *(float4*)(&hb[nxt][2 * HP]) = a0;
                *(float4*)(&hb[nxt][3 * HP]) = a1;
            }
        }

        // Emit cropped output
        if (emits) {
            float* ob = obase + (size_t)t * ostep;
            *(float4*)(ob)      = a0;
            *(float4*)(ob + NW) = a1;
        }

        __syncthreads();
        cur = nxt;
    }
}

extern "C" void kernel_launch(void* const* d_in, const int* in_sizes, int n_in,
                              void* d_out, int out_size) {
    const float* x  = (const float*)d_in[0];
    const float* Ak = (const float*)d_in[1];
    const float* Bk = (const float*)d_in[2];
    float* out = (float*)d_out;
    u_precompute<<<NT * NBC, 384>>>(x, Bk);
    convssm_scan<<<NBC, 512>>>(Ak, out);
}

// round 5
// speedup vs baseline: 1.9730x; 1.0378x over previous
#include <cuda_runtime.h>
#include <cuda_bf16.h>

// ConvSSM scan, spatial domain, two phases:
//   Phase 1 (u_precompute): U_t = B (*) x_t for all (t,b,c) — fully parallel.
//   Phase 2 (scan):         h_t = A (*) h_{t-1} + U_t  — 64 sequential steps,
//                           one CTA per (b,c) chain, h in SMEM with wrap halos.
//                           3x3 conv computed with packed fma.rn.f32x2.
// (*) = circular conv on the 64x64 torus (== reference's zero-padded FFT product).

#define NT 64
#define NB 2
#define NC 32
#define NH 32
#define NW 32
#define NBC 64            // NB*NC chains
#define UP 36             // U pitch (floats)
#define UROWS 36          // U stored rows (support is 34)
#define HP 72             // h smem pitch (floats)
#define HROWS 68          // h smem rows (idx = actual + 4, halo at idx 0..3)

// Scratch for U: (T*NBC) slices of 36x36 floats = 21.2 MB.
__device__ __align__(16) float g_U[(size_t)NT * NBC * UROWS * UP];

typedef unsigned long long u64;

__device__ __forceinline__ u64 pk(float lo, float hi) {
    u64 r; asm("mov.b64 %0, {%1, %2};" : "=l"(r) : "f"(lo), "f"(hi)); return r;
}
__device__ __forceinline__ u64 f2fma(u64 a, u64 b, u64 c) {
    u64 d; asm("fma.rn.f32x2 %0, %1, %2, %3;" : "=l"(d) : "l"(a), "l"(b), "l"(c));
    return d;
}

// ---------------------------------------------------------------------------
// Phase 1: U[n][r][c] = sum_{dy,dx} B[dy][dx] * x_n[r-dy][c-dx], zero-padded x.
// One CTA per (t,b,c) slice n. 384 threads, 324 active float4 outputs.
// ---------------------------------------------------------------------------
__global__ __launch_bounds__(384)
void u_precompute(const float* __restrict__ x, const float* __restrict__ Bk)
{
    __shared__ __align__(16) float xs[38 * 44];   // idx = actual + 2, zero border
    const int n   = blockIdx.x;           // n = t*NBC + bc
    const int c   = n & (NC - 1);         // channel
    const int tid = threadIdx.x;

    for (int i = tid; i < 38 * 44; i += 384) xs[i] = 0.0f;
    __syncthreads();

    const float2* xsl = (const float2*)(x + (size_t)n * (NH * NW));
    for (int i = tid; i < (NH * NW) / 2; i += 384) {
        const int r = i >> 4, c2 = (i & 15) * 2;
        float2 v = xsl[i];
        *(float2*)&xs[(r + 2) * 44 + c2 + 2] = v;
    }

    float Bw[9];
#pragma unroll
    for (int j = 0; j < 9; ++j) Bw[j] = Bk[c * 9 + j];
    __syncthreads();

    if (tid < UROWS * (UP / 4)) {
        const int r  = tid / (UP / 4);
        const int c4 = tid % (UP / 4);
        float o[4] = {0.f, 0.f, 0.f, 0.f};
#pragma unroll
        for (int dy = 0; dy < 3; ++dy) {
            const float* rp = &xs[(r + 2 - dy) * 44 + c4 * 4 + 2];
#pragma unroll
            for (int j = 0; j < 4; ++j)
#pragma unroll
                for (int dx = 0; dx < 3; ++dx)
                    o[j] = fmaf(Bw[dy * 3 + dx], rp[j - dx], o[j]);
        }
        float4 v = make_float4(o[0], o[1], o[2], o[3]);
        *(float4*)&g_U[(size_t)n * (UROWS * UP) + r * UP + c4 * 4] = v;
    }
}

// ---------------------------------------------------------------------------
// Phase 2: sequential scan. One CTA of 512 threads per (b,c) chain.
// h layout: hb[row_idx][col_idx], idx = actual + 4.
//   halo: col idx 0..3  <- actual cols 60..63, row idx 2..3 <- actual rows 62..63.
// Thread tile: 2 rows x 4 cols, processed as two column pairs with f32x2 FMA.
// ---------------------------------------------------------------------------
__global__ __launch_bounds__(512, 1)
void convssm_scan(const float* __restrict__ Ak, float* __restrict__ out)
{
    __shared__ __align__(16) float hb[2][HROWS * HP];

    const int tid  = threadIdx.x;
    const int tx   = tid & 15;
    const int ty   = tid >> 4;
    const int p    = ty & 1;
    const int k    = ty >> 1;
    const int row0 = 2 * k + 32 * p;
    const int col0 = tx << 2;
    const int bc   = blockIdx.x;
    const int c    = bc & (NC - 1);

    // A taps, packed {a,a} for f32x2.
    u64 A2[9];
#pragma unroll
    for (int j = 0; j < 9; ++j) { float a = Ak[c * 9 + j]; A2[j] = pk(a, a); }

    // h_{-1} = 0 (buffer 0 fully zeroed, including halos)
    for (int i = tid; i < HROWS * HP; i += 512) hb[0][i] = 0.0f;

    const bool uload = (row0 <= 34) && (tx <= 8);
    const bool emits = (p == 0) && (tx < 8);
    const bool chalo = (tx == 15);
    const bool rhalo = (row0 == 62);

    const float* Ubase = g_U + (size_t)bc * (UROWS * UP) + row0 * UP + col0;
    const size_t ustep = (size_t)NBC * (UROWS * UP);
    float* obase = out + (size_t)bc * (NH * NW) + row0 * NW + col0;
    const size_t ostep = (size_t)NBC * (NH * NW);

    // Prefetch U_0
    float4 uA = make_float4(0.f, 0.f, 0.f, 0.f), uB = uA;
    if (uload) {
        uA = *(const float4*)(Ubase);
        uB = *(const float4*)(Ubase + UP);
    }

    __syncthreads();

    int cur = 0;
    for (int t = 0; t < NT; ++t) {
        // Gather 4x6 patch rows as pairs:
        //   Q0=(p0,p1) Q1=(p2,p3) Q2=(p4,p5) aligned; S0=(p1,p2) S1=(p3,p4).
        const float* pb = &hb[cur][(row0 + 2) * HP + col0 + 2];
        u64 Q0[4], Q1[4], Q2[4], S0[4], S1[4];
#pragma unroll
        for (int i = 0; i < 4; ++i) {
            float2 q0 = *(const float2*)(pb + i * HP);
            float2 q1 = *(const float2*)(pb + i * HP + 2);
            float2 q2 = *(const float2*)(pb + i * HP + 4);
            Q0[i] = pk(q0.x, q0.y);
            Q1[i] = pk(q1.x, q1.y);
            Q2[i] = pk(q2.x, q2.y);
            S0[i] = pk(q0.y, q1.x);
            S1[i] = pk(q1.y, q2.x);
        }

        // acc = U_t + A (*) h_{t-1}, two output rows x two column pairs.
        u64 accL[2], accR[2];
        accL[0] = pk(uA.x, uA.y); accR[0] = pk(uA.z, uA.w);
        accL[1] = pk(uB.x, uB.y); accR[1] = pk(uB.z, uB.w);
#pragma unroll
        for (int r = 0; r < 2; ++r) {
#pragma unroll
            for (int dy = 0; dy < 3; ++dy) {
                const int pi = r + 2 - dy;       // patch row index
                accL[r] = f2fma(A2[dy * 3 + 0], Q1[pi], accL[r]);
                accL[r] = f2fma(A2[dy * 3 + 1], S0[pi], accL[r]);
                accL[r] = f2fma(A2[dy * 3 + 2], Q0[pi], accL[r]);
                accR[r] = f2fma(A2[dy * 3 + 0], Q2[pi], accR[r]);
                accR[r] = f2fma(A2[dy * 3 + 1], S1[pi], accR[r]);
                accR[r] = f2fma(A2[dy * 3 + 2], Q1[pi], accR[r]);
            }
        }

        // Prefetch U_{t+1}
        if (uload && t + 1 < NT) {
            const float* up = Ubase + (size_t)(t + 1) * ustep;
            uA = *(const float4*)(up);
            uB = *(const float4*)(up + UP);
        }

        // Write h_t (+ wrap halos), 16B stores of pair registers.
        const int nxt = cur ^ 1;
        ulonglong2 r0 = make_ulonglong2(accL[0], accR[0]);
        ulonglong2 r1 = make_ulonglong2(accL[1], accR[1]);
        float* wb = &hb[nxt][(row0 + 4) * HP + col0 + 4];
        *(ulonglong2*)(wb)      = r0;
        *(ulonglong2*)(wb + HP) = r1;
        if (chalo) {                       // actual cols 60..63 -> col idx 0..3
            *(ulonglong2*)(wb - 64)      = r0;
            *(ulonglong2*)(wb - 64 + HP) = r1;
        }
        if (rhalo) {                       // actual rows 62..63 -> row idx 2..3
            float* hw = &hb[nxt][2 * HP + col0 + 4];
            *(ulonglong2*)(hw)      = r0;
            *(ulonglong2*)(hw + HP) = r1;
            if (chalo) {
                *(ulonglong2*)(&hb[nxt][2 * HP]) = r0;
                *(ulonglong2*)(&hb[nxt][3 * HP]) = r1;
            }
        }

        // Emit cropped output
        if (emits) {
            float* ob = obase + (size_t)t * ostep;
            *(ulonglong2*)(ob)      = r0;
            *(ulonglong2*)(ob + NW) = r1;
        }

        __syncthreads();
        cur = nxt;
    }
}

extern "C" void kernel_launch(void* const* d_in, const int* in_sizes, int n_in,
                              void* d_out, int out_size) {
    const float* x  = (const float*)d_in[0];
    const float* Ak = (const float*)d_in[1];
    const float* Bk = (const float*)d_in[2];
    float* out = (float*)d_out;
    u_precompute<<<NT * NBC, 384>>>(x, Bk);
    convssm_scan<<<NBC, 512>>>(Ak, out);
}

// round 6
// speedup vs baseline: 2.3020x; 1.1668x over previous
#include <cuda_runtime.h>
#include <cuda_bf16.h>

// ConvSSM scan, spatial domain.
//   Phase 1: U_t = B (*) x_t for all (t,b,c)  — fully parallel, to scratch.
//   Phase 2: h_t = A (*) h_{t-1} + U_t        — 64 sequential steps, one CTA
//            per (b,c). h lives in REGISTERS (warp w owns rows 4w..4w+3,
//            lane l owns cols 2l,2l+1). Horizontal neighbors via shfl (torus
//            wrap = circular lane shift); vertical halo (2 rows/warp) via
//            double-buffered SMEM; one barrier per step. Conv in fma.rn.f32x2.
// (*) = circular conv on the 64x64 torus (== reference's zero-padded FFT product).

#define NT 64
#define NB 2
#define NC 32
#define NH 32
#define NW 32
#define NBC 64            // NB*NC chains
#define UP 36             // U pitch (floats)
#define UROWS 34          // U rows (support = 34)

// Scratch for U: NT+1 slices (extra slice = guard for unconditional prefetch).
__device__ __align__(16) float g_U[(size_t)(NT + 1) * NBC * UROWS * UP];

typedef unsigned long long u64;

__device__ __forceinline__ u64 pk(float lo, float hi) {
    u64 r; asm("mov.b64 %0, {%1, %2};" : "=l"(r) : "f"(lo), "f"(hi)); return r;
}
__device__ __forceinline__ float2 unpk(u64 v) {
    float2 f; asm("mov.b64 {%0, %1}, %2;" : "=f"(f.x), "=f"(f.y) : "l"(v)); return f;
}
__device__ __forceinline__ u64 f2fma(u64 a, u64 b, u64 c) {
    u64 d; asm("fma.rn.f32x2 %0, %1, %2, %3;" : "=l"(d) : "l"(a), "l"(b), "l"(c));
    return d;
}

// Build the three column-pair operands for one input row:
//   O0 = {x, x+1}, O1 = {x-1, x}, O2 = {x-2, x-1}  (left cols via circular shfl)
__device__ __forceinline__ void mkops(float2 P, int src, u64& O0, u64& O1, u64& O2) {
    float Lx = __shfl_sync(0xffffffffu, P.x, src);
    float Ly = __shfl_sync(0xffffffffu, P.y, src);
    O0 = pk(P.x, P.y);
    O1 = pk(Ly, P.x);
    O2 = pk(Lx, Ly);
}
// acc += A[dy][0]*O0 + A[dy][1]*O1 + A[dy][2]*O2
__device__ __forceinline__ u64 cdy(const u64* A2, int dy, u64 O0, u64 O1, u64 O2, u64 acc) {
    acc = f2fma(A2[3 * dy + 0], O0, acc);
    acc = f2fma(A2[3 * dy + 1], O1, acc);
    acc = f2fma(A2[3 * dy + 2], O2, acc);
    return acc;
}

// ---------------------------------------------------------------------------
// Phase 1: U[n][r][c] = sum B[dy][dx] * x_n[r-dy][c-dx], zero-padded x.
// One CTA per (t,b,c) slice n. 384 threads, 306 active float4 outputs.
// ---------------------------------------------------------------------------
__global__ __launch_bounds__(384)
void u_precompute(const float* __restrict__ x, const float* __restrict__ Bk)
{
    __shared__ __align__(16) float xs[38 * 44];   // idx = actual + 2, zero border
    const int n   = blockIdx.x;           // n = t*NBC + bc
    const int c   = n & (NC - 1);
    const int tid = threadIdx.x;

    for (int i = tid; i < 38 * 44; i += 384) xs[i] = 0.0f;
    __syncthreads();

    const float2* xsl = (const float2*)(x + (size_t)n * (NH * NW));
    for (int i = tid; i < (NH * NW) / 2; i += 384) {
        const int r = i >> 4, c2 = (i & 15) * 2;
        float2 v = xsl[i];
        *(float2*)&xs[(r + 2) * 44 + c2 + 2] = v;
    }

    float Bw[9];
#pragma unroll
    for (int j = 0; j < 9; ++j) Bw[j] = Bk[c * 9 + j];
    __syncthreads();

    if (tid < UROWS * (UP / 4)) {
        const int r  = tid / (UP / 4);
        const int c4 = tid % (UP / 4);
        float o[4] = {0.f, 0.f, 0.f, 0.f};
#pragma unroll
        for (int dy = 0; dy < 3; ++dy) {
            const float* rp = &xs[(r + 2 - dy) * 44 + c4 * 4 + 2];
#pragma unroll
            for (int j = 0; j < 4; ++j)
#pragma unroll
                for (int dx = 0; dx < 3; ++dx)
                    o[j] = fmaf(Bw[dy * 3 + dx], rp[j - dx], o[j]);
        }
        float4 v = make_float4(o[0], o[1], o[2], o[3]);
        *(float4*)&g_U[(size_t)n * (UROWS * UP) + r * UP + c4 * 4] = v;
    }
}

// ---------------------------------------------------------------------------
// Phase 2: register-resident scan. 512 threads = 16 warps per CTA, 1 CTA/(b,c).
// ---------------------------------------------------------------------------
__global__ __launch_bounds__(512, 1)
void convssm_scan(const float* __restrict__ Ak, float* __restrict__ out)
{
    __shared__ __align__(16) float halo[2][32 * 64];  // 2 rows per warp, dbl-buffered

    const int tid  = threadIdx.x;
    const int lane = tid & 31;
    const int w    = tid >> 5;
    const int bc   = blockIdx.x;
    const int c    = bc & (NC - 1);
    const int src  = (lane + 31) & 31;     // circular left neighbor
    const int row0 = 4 * w;

    u64 A2[9];
#pragma unroll
    for (int j = 0; j < 9; ++j) { float a = Ak[c * 9 + j]; A2[j] = pk(a, a); }

    // State h_{-1} = 0
    float2 h[4];
#pragma unroll
    for (int i = 0; i < 4; ++i) h[i] = make_float2(0.f, 0.f);

    for (int i = tid; i < 32 * 64; i += 512) halo[0][i] = 0.0f;

    // U pointers (per owned row), predicate = inside 34x34 support.
    const float* ub = g_U + (size_t)bc * (UROWS * UP) + 2 * lane;
    const size_t ustep = (size_t)NBC * (UROWS * UP);
    bool ul[4];
    const float* p[4];
#pragma unroll
    for (int i = 0; i < 4; ++i) {
        ul[i] = (lane <= 16) && (row0 + i < UROWS);
        p[i]  = ub + (size_t)(row0 + i) * UP;
    }

    // Prefetch U_0
    u64 u[4];
#pragma unroll
    for (int i = 0; i < 4; ++i) u[i] = ul[i] ? *(const u64*)p[i] : 0ull;

    float* ob = out + (size_t)bc * (NH * NW) + row0 * NW + 2 * lane;
    const bool emits = (w < 8) && (lane < 16);
    const int wslot = 2 * w;                       // rows 4w+2, 4w+3
    const int rslot = 2 * ((w + 15) & 15);         // rows 4w-2, 4w-1 (circular)

    __syncthreads();

    int cur = 0;
#pragma unroll 2
    for (int t = 0; t < NT; ++t) {
        // Vertical halo rows (h_{t-1} rows 4w-2, 4w-1)
        float2 Hm2 = *(const float2*)&halo[cur][rslot * 64 + 2 * lane];
        float2 Hm1 = *(const float2*)&halo[cur][(rslot + 1) * 64 + 2 * lane];

        // Prefetch U_{t+1} (guard slice exists; values unused at t=NT-1)
        u64 un[4];
#pragma unroll
        for (int i = 0; i < 4; ++i) {
            p[i] += ustep;
            un[i] = ul[i] ? *(const u64*)p[i] : 0ull;
        }

        // acc = U_t + A (*) h_{t-1}
        u64 acc0 = u[0], acc1 = u[1], acc2 = u[2], acc3 = u[3];
        u64 O0, O1, O2;
        mkops(Hm2, src, O0, O1, O2);   // input row -2
        acc0 = cdy(A2, 2, O0, O1, O2, acc0);
        mkops(Hm1, src, O0, O1, O2);   // input row -1
        acc0 = cdy(A2, 1, O0, O1, O2, acc0);
        acc1 = cdy(A2, 2, O0, O1, O2, acc1);
        mkops(h[0], src, O0, O1, O2);  // input row 0
        acc0 = cdy(A2, 0, O0, O1, O2, acc0);
        acc1 = cdy(A2, 1, O0, O1, O2, acc1);
        acc2 = cdy(A2, 2, O0, O1, O2, acc2);
        mkops(h[1], src, O0, O1, O2);  // input row 1
        acc1 = cdy(A2, 0, O0, O1, O2, acc1);
        acc2 = cdy(A2, 1, O0, O1, O2, acc2);
        acc3 = cdy(A2, 2, O0, O1, O2, acc3);
        mkops(h[2], src, O0, O1, O2);  // input row 2
        acc2 = cdy(A2, 0, O0, O1, O2, acc2);
        acc3 = cdy(A2, 1, O0, O1, O2, acc3);
        mkops(h[3], src, O0, O1, O2);  // input row 3
        acc3 = cdy(A2, 0, O0, O1, O2, acc3);

        // New state
        h[0] = unpk(acc0); h[1] = unpk(acc1); h[2] = unpk(acc2); h[3] = unpk(acc3);

        // Publish bottom-2 halo rows for the warp below
        const int nxt = cur ^ 1;
        *(u64*)&halo[nxt][wslot * 64 + 2 * lane]       = acc2;
        *(u64*)&halo[nxt][(wslot + 1) * 64 + 2 * lane] = acc3;

        // Emit cropped 32x32 output
        if (emits) {
            float* o = ob + (size_t)t * (NBC * NH * NW);
            *(u64*)(o)          = acc0;
            *(u64*)(o + NW)     = acc1;
            *(u64*)(o + 2 * NW) = acc2;
            *(u64*)(o + 3 * NW) = acc3;
        }

        u[0] = un[0]; u[1] = un[1]; u[2] = un[2]; u[3] = un[3];

        __syncthreads();
        cur = nxt;
    }
}

extern "C" void kernel_launch(void* const* d_in, const int* in_sizes, int n_in,
                              void* d_out, int out_size) {
    const float* x  = (const float*)d_in[0];
    const float* Ak = (const float*)d_in[1];
    const float* Bk = (const float*)d_in[2];
    float* out = (float*)d_out;
    u_precompute<<<NT * NBC, 384>>>(x, Bk);
    convssm_scan<<<NBC, 512>>>(Ak, out);
}